// round 1
// baseline (speedup 1.0000x reference)
#include <cuda_runtime.h>
#include <cuda_bf16.h>
#include <math.h>

#define NN 50000
#define NE 800000
#define DI 128
#define DH 128
#define DO 64

// ---------------- device scratch (static globals: allocation-free) ----------------
__device__ float g_B1[NN * 128];   // hs1 (layer1 scaled hidden), later h2s (layer2, 64-wide)
__device__ float g_B2[NN * 128];   // y1 = relu(agg1*dis + b1)
__device__ float g_dis[NN];        // deg^{-1/2} (deg includes self loop)
__device__ int   g_cnt[NN];        // in-degree histogram (excl self loop)
__device__ int   g_off[NN + 1];    // CSR offsets by destination
__device__ int   g_cur[NN];        // placement cursors
__device__ int   g_src[NE];        // source node per CSR slot

// ---------------- CSR build ----------------
__global__ void k_zero_cnt(int n) {
    int i = blockIdx.x * blockDim.x + threadIdx.x;
    if (i < n) g_cnt[i] = 0;
}

__global__ void k_hist(const int* __restrict__ col, int e) {
    int i = blockIdx.x * blockDim.x + threadIdx.x;
    if (i < e) atomicAdd(&g_cnt[col[i]], 1);
}

// single-block scan over NN bins; also computes dis and init cursors
__global__ void k_scan(int n, int e) {
    __shared__ int sbuf[1024];
    int tid = threadIdx.x;
    const int CH = (n + 1023) / 1024;
    int beg = tid * CH;
    int end = beg + CH; if (end > n) end = n;
    int sum = 0;
    for (int i = beg; i < end; i++) sum += g_cnt[i];
    sbuf[tid] = sum;
    __syncthreads();
    for (int d = 1; d < 1024; d <<= 1) {
        int t = (tid >= d) ? sbuf[tid - d] : 0;
        __syncthreads();
        sbuf[tid] += t;
        __syncthreads();
    }
    int base = sbuf[tid] - sum;  // exclusive prefix
    for (int i = beg; i < end; i++) {
        int c = g_cnt[i];
        g_off[i] = base;
        g_cur[i] = base;
        g_dis[i] = rsqrtf((float)(c + 1));   // +1 for self loop
        base += c;
    }
    if (tid == 0) g_off[n] = e;
}

__global__ void k_place(const int* __restrict__ row, const int* __restrict__ col, int e) {
    int i = blockIdx.x * blockDim.x + threadIdx.x;
    if (i < e) {
        int c = col[i];
        int p = atomicAdd(&g_cur[c], 1);
        g_src[p] = row[i];
    }
}

// ---------------- GEMM: out[r] = dis[r] * (A[r] @ W), K = 128 ----------------
// 32 rows x NOUT cols per block, 128 threads, W staged in smem 64 cols at a time.
template<int NOUT>
__global__ void k_gemm(const float* __restrict__ A, const float* __restrict__ W,
                       float* __restrict__ outp, int n) {
    __shared__ float Wsh[128 * 64];  // 32KB
    __shared__ float Xs[32 * 128];   // 16KB
    int tid  = threadIdx.x;
    int row0 = blockIdx.x * 32;

    // stage X tile: 32x128 floats = 1024 float4
    const float4* A4 = (const float4*)A;
    #pragma unroll
    for (int i = 0; i < 8; i++) {
        int idx = tid + i * 128;           // float4 index 0..1023
        int r = idx >> 5;                  // 32 float4 per row
        int c = idx & 31;
        float4 v = make_float4(0.f, 0.f, 0.f, 0.f);
        if (row0 + r < n) v = A4[(size_t)(row0 + r) * 32 + c];
        ((float4*)Xs)[idx] = v;
    }

    const int NH = (NOUT == 128) ? 2 : 1;
    int tx = tid & 15;        // col group: 4 cols each
    int ty = tid >> 4;        // row group: 4 rows each

    const float4* W4 = (const float4*)W;
    for (int h = 0; h < NH; h++) {
        __syncthreads();
        // stage W half: 128 x 64 floats = 2048 float4
        #pragma unroll
        for (int i = 0; i < 16; i++) {
            int idx = tid + i * 128;       // 0..2047
            int k = idx >> 4;              // 16 float4 per 64-col row
            int c = idx & 15;
            ((float4*)Wsh)[idx] = W4[(size_t)k * (NOUT / 4) + h * 16 + c];
        }
        __syncthreads();

        float acc0x = 0, acc0y = 0, acc0z = 0, acc0w = 0;
        float acc1x = 0, acc1y = 0, acc1z = 0, acc1w = 0;
        float acc2x = 0, acc2y = 0, acc2z = 0, acc2w = 0;
        float acc3x = 0, acc3y = 0, acc3z = 0, acc3w = 0;

        #pragma unroll 4
        for (int k = 0; k < 128; k++) {
            float a0 = Xs[(ty * 4 + 0) * 128 + k];
            float a1 = Xs[(ty * 4 + 1) * 128 + k];
            float a2 = Xs[(ty * 4 + 2) * 128 + k];
            float a3 = Xs[(ty * 4 + 3) * 128 + k];
            float4 b = ((float4*)Wsh)[k * 16 + tx];
            acc0x += a0 * b.x; acc0y += a0 * b.y; acc0z += a0 * b.z; acc0w += a0 * b.w;
            acc1x += a1 * b.x; acc1y += a1 * b.y; acc1z += a1 * b.z; acc1w += a1 * b.w;
            acc2x += a2 * b.x; acc2y += a2 * b.y; acc2z += a2 * b.z; acc2w += a2 * b.w;
            acc3x += a3 * b.x; acc3y += a3 * b.y; acc3z += a3 * b.z; acc3w += a3 * b.w;
        }

        float4* O4 = (float4*)outp;
        #pragma unroll
        for (int i = 0; i < 4; i++) {
            int r = row0 + ty * 4 + i;
            if (r < n) {
                float s = g_dis[r];
                float4 o;
                if (i == 0) o = make_float4(acc0x * s, acc0y * s, acc0z * s, acc0w * s);
                else if (i == 1) o = make_float4(acc1x * s, acc1y * s, acc1z * s, acc1w * s);
                else if (i == 2) o = make_float4(acc2x * s, acc2y * s, acc2z * s, acc2w * s);
                else o = make_float4(acc3x * s, acc3y * s, acc3z * s, acc3w * s);
                O4[(size_t)r * (NOUT / 4) + h * 16 + tx] = o;
            }
        }
    }
}

// ---------------- gather (warp per node): out[v] = act( dis[v]*(hs[v] + sum_in hs[r]) + bias ) ----------------
__global__ void k_gather128(const float* __restrict__ hs, const float* __restrict__ bias,
                            float* __restrict__ outp, int n, int relu) {
    int w = (blockIdx.x * blockDim.x + threadIdx.x) >> 5;
    if (w >= n) return;
    int lane = threadIdx.x & 31;
    const float4* hs4 = (const float4*)hs;
    float4 acc = hs4[(size_t)w * 32 + lane];     // self loop
    int s = g_off[w], e = g_off[w + 1];
    int j = s;
    for (; j + 1 < e; j += 2) {
        int r0 = __ldg(&g_src[j]);
        int r1 = __ldg(&g_src[j + 1]);
        float4 m0 = hs4[(size_t)r0 * 32 + lane];
        float4 m1 = hs4[(size_t)r1 * 32 + lane];
        acc.x += m0.x + m1.x; acc.y += m0.y + m1.y;
        acc.z += m0.z + m1.z; acc.w += m0.w + m1.w;
    }
    if (j < e) {
        int r = __ldg(&g_src[j]);
        float4 m = hs4[(size_t)r * 32 + lane];
        acc.x += m.x; acc.y += m.y; acc.z += m.z; acc.w += m.w;
    }
    float sc = g_dis[w];
    float4 b = ((const float4*)bias)[lane];
    float4 o = make_float4(acc.x * sc + b.x, acc.y * sc + b.y,
                           acc.z * sc + b.z, acc.w * sc + b.w);
    if (relu) {
        o.x = fmaxf(o.x, 0.f); o.y = fmaxf(o.y, 0.f);
        o.z = fmaxf(o.z, 0.f); o.w = fmaxf(o.w, 0.f);
    }
    ((float4*)outp)[(size_t)w * 32 + lane] = o;
}

__global__ void k_gather64(const float* __restrict__ hs, const float* __restrict__ bias,
                           float* __restrict__ outp, int n) {
    int w = (blockIdx.x * blockDim.x + threadIdx.x) >> 5;
    if (w >= n) return;
    int lane = threadIdx.x & 31;
    const float2* hs2 = (const float2*)hs;
    float2 acc = hs2[(size_t)w * 32 + lane];     // self loop
    int s = g_off[w], e = g_off[w + 1];
    int j = s;
    for (; j + 1 < e; j += 2) {
        int r0 = __ldg(&g_src[j]);
        int r1 = __ldg(&g_src[j + 1]);
        float2 m0 = hs2[(size_t)r0 * 32 + lane];
        float2 m1 = hs2[(size_t)r1 * 32 + lane];
        acc.x += m0.x + m1.x; acc.y += m0.y + m1.y;
    }
    if (j < e) {
        int r = __ldg(&g_src[j]);
        float2 m = hs2[(size_t)r * 32 + lane];
        acc.x += m.x; acc.y += m.y;
    }
    float sc = g_dis[w];
    float2 b = ((const float2*)bias)[lane];
    float2 o = make_float2(acc.x * sc + b.x, acc.y * sc + b.y);
    ((float2*)outp)[(size_t)w * 32 + lane] = o;
}

// ---------------- launch ----------------
extern "C" void kernel_launch(void* const* d_in, const int* in_sizes, int n_in,
                              void* d_out, int out_size) {
    const float* x   = (const float*)d_in[0];
    const int*   ei  = (const int*)d_in[1];
    const float* W1  = (const float*)d_in[2];
    const float* b1  = (const float*)d_in[3];
    const float* W2  = (const float*)d_in[4];
    const float* b2  = (const float*)d_in[5];
    float* out = (float*)d_out;

    const int n = in_sizes[0] / DI;     // 50000
    const int e = in_sizes[1] / 2;      // 800000
    const int* row = ei;
    const int* col = ei + e;

    float* B1 = nullptr; float* B2 = nullptr;
    cudaGetSymbolAddress((void**)&B1, g_B1);
    cudaGetSymbolAddress((void**)&B2, g_B2);

    // CSR build
    k_zero_cnt<<<(n + 255) / 256, 256>>>(n);
    k_hist<<<(e + 255) / 256, 256>>>(col, e);
    k_scan<<<1, 1024>>>(n, e);
    k_place<<<(e + 255) / 256, 256>>>(row, col, e);

    // layer 1: B1 = dis * (x @ W1); B2 = relu(dis * gather(B1) + b1)
    k_gemm<128><<<(n + 31) / 32, 128>>>(x, W1, B1, n);
    k_gather128<<<(n * 32 + 255) / 256, 256>>>(B1, b1, B2, n, 1);

    // layer 2: B1 = dis * (B2 @ W2); out = dis * gather(B1) + b2
    k_gemm<64><<<(n + 31) / 32, 128>>>(B2, W2, B1, n);
    k_gather64<<<(n * 32 + 255) / 256, 256>>>(B1, b2, out, n);
}

// round 2
// speedup vs baseline: 1.0555x; 1.0555x over previous
#include <cuda_runtime.h>
#include <cuda_bf16.h>
#include <math.h>

#define NN 50000
#define NE 800000
#define DI 128
#define DH 128
#define DO 64

typedef unsigned long long ull;

// ---------------- device scratch ----------------
__device__ float g_B1[NN * 128];   // scaled hidden (dis * XW)
__device__ float g_B2[NN * 128];   // y1 = relu(...)
__device__ float g_dis[NN];        // deg^{-1/2} (incl self loop)
__device__ int   g_cnt[NN];
__device__ int   g_off[NN + 1];
__device__ int   g_cur[NN];
__device__ int   g_src[NE];

// ---------------- packed f32x2 helpers ----------------
__device__ __forceinline__ void ffma2(ull &d, ull a, ull b) {
    asm("fma.rn.f32x2 %0, %1, %2, %0;" : "+l"(d) : "l"(a), "l"(b));
}
__device__ __forceinline__ ull pack2(float x, float y) {
    ull r; asm("mov.b64 %0, {%1, %2};" : "=l"(r) : "f"(x), "f"(y)); return r;
}
__device__ __forceinline__ void unpack2(float &x, float &y, ull v) {
    asm("mov.b64 {%0, %1}, %2;" : "=f"(x), "=f"(y) : "l"(v));
}

// ---------------- CSR build ----------------
__global__ void k_hist(const int* __restrict__ col, int e) {
    int i = blockIdx.x * blockDim.x + threadIdx.x;
    if (i < e) atomicAdd(&g_cnt[col[i]], 1);
}

__global__ void k_scan(int n, int e) {
    __shared__ int sbuf[1024];
    int tid = threadIdx.x;
    const int CH = (n + 1023) / 1024;
    int beg = tid * CH;
    int end = beg + CH; if (end > n) end = n;
    int sum = 0;
    for (int i = beg; i < end; i++) sum += g_cnt[i];
    sbuf[tid] = sum;
    __syncthreads();
    for (int d = 1; d < 1024; d <<= 1) {
        int t = (tid >= d) ? sbuf[tid - d] : 0;
        __syncthreads();
        sbuf[tid] += t;
        __syncthreads();
    }
    int base = sbuf[tid] - sum;  // exclusive prefix
    for (int i = beg; i < end; i++) {
        int c = g_cnt[i];
        g_off[i] = base;
        g_cur[i] = base;
        g_dis[i] = rsqrtf((float)(c + 1));
        base += c;
    }
    if (tid == 0) g_off[n] = e;
}

__global__ void k_place(const int* __restrict__ row, const int* __restrict__ col, int e) {
    int i = blockIdx.x * blockDim.x + threadIdx.x;
    if (i < e) {
        int c = col[i];
        int p = atomicAdd(&g_cur[c], 1);
        g_src[p] = row[i];
    }
}

// ---------------- GEMM via fma.rn.f32x2 ----------------
// Block: 256 threads. NOUT=128: tile 64 rows x 128 cols. NOUT=64: tile 128 rows x 64 cols.
// Thread tile: 8 rows x 4 cols (2 col-pairs), K=128 fully staged.
// X staged TRANSPOSED in smem (Xs[k][r]) so a-loads are 2 broadcast LDS.128.
// Whole W resident in smem. Epilogue scales row by g_dis[row].
template<int NOUT>
__global__ void __launch_bounds__(256, 2) k_gemm(const float* __restrict__ A,
                                                 const float* __restrict__ W,
                                                 float* __restrict__ outp, int n) {
    constexpr int COLG = NOUT / 4;       // col groups (4 cols each)
    constexpr int RG   = 256 / COLG;     // row groups
    constexpr int ROWS_T = RG * 8;       // rows per block tile (64 or 128)

    extern __shared__ float smem[];
    float* Xs  = smem;                   // [128][ROWS_T] transposed
    float* Wsh = smem + 128 * ROWS_T;    // [128][NOUT] row-major

    int tid  = threadIdx.x;
    int row0 = blockIdx.x * ROWS_T;

    // stage W (row-major copy)
    {
        const float4* W4 = (const float4*)W;
        float4* Wsh4 = (float4*)Wsh;
        #pragma unroll
        for (int i = 0; i < NOUT / 8; i++) {
            int idx = tid + i * 256;     // total 32*NOUT float4
            Wsh4[idx] = W4[idx];
        }
    }

    // stage X transposed: read float4 along k, scatter into Xs[k][r]
    {
        const float4* A4 = (const float4*)A;
        #pragma unroll
        for (int i = 0; i < ROWS_T / 8; i++) {
            int idx = tid + i * 256;         // 0 .. ROWS_T*32-1
            int r = idx % ROWS_T;            // consecutive lanes -> consecutive r
            int c = idx / ROWS_T;            // float4 index along k
            float4 v = make_float4(0.f, 0.f, 0.f, 0.f);
            if (row0 + r < n) v = A4[(size_t)(row0 + r) * 32 + c];
            Xs[(4 * c + 0) * ROWS_T + r] = v.x;
            Xs[(4 * c + 1) * ROWS_T + r] = v.y;
            Xs[(4 * c + 2) * ROWS_T + r] = v.z;
            Xs[(4 * c + 3) * ROWS_T + r] = v.w;
        }
    }
    __syncthreads();

    int cg = tid % COLG;                 // col group -> cols cg*4 .. cg*4+3
    int rg = tid / COLG;                 // row group -> rows rg*8 .. rg*8+7

    ull acc[16];
    #pragma unroll
    for (int i = 0; i < 16; i++) acc[i] = 0ull;   // 0ull == packed (0.f, 0.f)

    #pragma unroll 4
    for (int k = 0; k < 128; k++) {
        const float* xr = &Xs[k * ROWS_T + rg * 8];
        float4 a0 = *(const float4*)xr;
        float4 a1 = *(const float4*)(xr + 4);
        float4 bv = *(const float4*)&Wsh[k * NOUT + cg * 4];
        ull bl = pack2(bv.x, bv.y);
        ull bh = pack2(bv.z, bv.w);
        ull t;
        t = pack2(a0.x, a0.x); ffma2(acc[0], t, bl); ffma2(acc[8],  t, bh);
        t = pack2(a0.y, a0.y); ffma2(acc[1], t, bl); ffma2(acc[9],  t, bh);
        t = pack2(a0.z, a0.z); ffma2(acc[2], t, bl); ffma2(acc[10], t, bh);
        t = pack2(a0.w, a0.w); ffma2(acc[3], t, bl); ffma2(acc[11], t, bh);
        t = pack2(a1.x, a1.x); ffma2(acc[4], t, bl); ffma2(acc[12], t, bh);
        t = pack2(a1.y, a1.y); ffma2(acc[5], t, bl); ffma2(acc[13], t, bh);
        t = pack2(a1.z, a1.z); ffma2(acc[6], t, bl); ffma2(acc[14], t, bh);
        t = pack2(a1.w, a1.w); ffma2(acc[7], t, bl); ffma2(acc[15], t, bh);
    }

    // epilogue: scale by dis[row], store float4
    float4* O4 = (float4*)outp;
    #pragma unroll
    for (int i = 0; i < 8; i++) {
        int r = row0 + rg * 8 + i;
        if (r < n) {
            float s = g_dis[r];
            float c0, c1, c2, c3;
            unpack2(c0, c1, acc[i]);
            unpack2(c2, c3, acc[8 + i]);
            O4[(size_t)r * (NOUT / 4) + cg] =
                make_float4(c0 * s, c1 * s, c2 * s, c3 * s);
        }
    }
}

// ---------------- gather (warp per node) ----------------
__global__ void k_gather128(const float* __restrict__ hs, const float* __restrict__ bias,
                            float* __restrict__ outp, int n, int relu) {
    int w = (blockIdx.x * blockDim.x + threadIdx.x) >> 5;
    if (w >= n) return;
    int lane = threadIdx.x & 31;
    const float4* hs4 = (const float4*)hs;
    float4 acc = hs4[(size_t)w * 32 + lane];     // self loop
    int s = g_off[w], e = g_off[w + 1];
    int j = s;
    for (; j + 4 <= e; j += 4) {
        int r0 = __ldg(&g_src[j]);
        int r1 = __ldg(&g_src[j + 1]);
        int r2 = __ldg(&g_src[j + 2]);
        int r3 = __ldg(&g_src[j + 3]);
        float4 m0 = hs4[(size_t)r0 * 32 + lane];
        float4 m1 = hs4[(size_t)r1 * 32 + lane];
        float4 m2 = hs4[(size_t)r2 * 32 + lane];
        float4 m3 = hs4[(size_t)r3 * 32 + lane];
        acc.x += (m0.x + m1.x) + (m2.x + m3.x);
        acc.y += (m0.y + m1.y) + (m2.y + m3.y);
        acc.z += (m0.z + m1.z) + (m2.z + m3.z);
        acc.w += (m0.w + m1.w) + (m2.w + m3.w);
    }
    for (; j < e; j++) {
        int r = __ldg(&g_src[j]);
        float4 m = hs4[(size_t)r * 32 + lane];
        acc.x += m.x; acc.y += m.y; acc.z += m.z; acc.w += m.w;
    }
    float sc = g_dis[w];
    float4 b = ((const float4*)bias)[lane];
    float4 o = make_float4(acc.x * sc + b.x, acc.y * sc + b.y,
                           acc.z * sc + b.z, acc.w * sc + b.w);
    if (relu) {
        o.x = fmaxf(o.x, 0.f); o.y = fmaxf(o.y, 0.f);
        o.z = fmaxf(o.z, 0.f); o.w = fmaxf(o.w, 0.f);
    }
    ((float4*)outp)[(size_t)w * 32 + lane] = o;
}

__global__ void k_gather64(const float* __restrict__ hs, const float* __restrict__ bias,
                           float* __restrict__ outp, int n) {
    int w = (blockIdx.x * blockDim.x + threadIdx.x) >> 5;
    if (w >= n) return;
    int lane = threadIdx.x & 31;
    const float2* hs2 = (const float2*)hs;
    float2 acc = hs2[(size_t)w * 32 + lane];     // self loop
    int s = g_off[w], e = g_off[w + 1];
    int j = s;
    for (; j + 4 <= e; j += 4) {
        int r0 = __ldg(&g_src[j]);
        int r1 = __ldg(&g_src[j + 1]);
        int r2 = __ldg(&g_src[j + 2]);
        int r3 = __ldg(&g_src[j + 3]);
        float2 m0 = hs2[(size_t)r0 * 32 + lane];
        float2 m1 = hs2[(size_t)r1 * 32 + lane];
        float2 m2 = hs2[(size_t)r2 * 32 + lane];
        float2 m3 = hs2[(size_t)r3 * 32 + lane];
        acc.x += (m0.x + m1.x) + (m2.x + m3.x);
        acc.y += (m0.y + m1.y) + (m2.y + m3.y);
    }
    for (; j < e; j++) {
        int r = __ldg(&g_src[j]);
        float2 m = hs2[(size_t)r * 32 + lane];
        acc.x += m.x; acc.y += m.y;
    }
    float sc = g_dis[w];
    float2 b = ((const float2*)bias)[lane];
    float2 o = make_float2(acc.x * sc + b.x, acc.y * sc + b.y);
    ((float2*)outp)[(size_t)w * 32 + lane] = o;
}

// ---------------- launch ----------------
extern "C" void kernel_launch(void* const* d_in, const int* in_sizes, int n_in,
                              void* d_out, int out_size) {
    const float* x   = (const float*)d_in[0];
    const int*   ei  = (const int*)d_in[1];
    const float* W1  = (const float*)d_in[2];
    const float* b1  = (const float*)d_in[3];
    const float* W2  = (const float*)d_in[4];
    const float* b2  = (const float*)d_in[5];
    float* out = (float*)d_out;

    const int n = in_sizes[0] / DI;     // 50000
    const int e = in_sizes[1] / 2;      // 800000
    const int* row = ei;
    const int* col = ei + e;

    float* B1 = nullptr; float* B2 = nullptr; int* cnt = nullptr;
    cudaGetSymbolAddress((void**)&B1, g_B1);
    cudaGetSymbolAddress((void**)&B2, g_B2);
    cudaGetSymbolAddress((void**)&cnt, g_cnt);

    const int SMEM = (128 * 64 + 128 * 128) * 4;   // 98304 bytes (same both variants)
    cudaFuncSetAttribute(k_gemm<128>, cudaFuncAttributeMaxDynamicSharedMemorySize, SMEM);
    cudaFuncSetAttribute(k_gemm<64>,  cudaFuncAttributeMaxDynamicSharedMemorySize, SMEM);

    // CSR build
    cudaMemsetAsync(cnt, 0, n * sizeof(int));
    k_hist<<<(e + 255) / 256, 256>>>(col, e);
    k_scan<<<1, 1024>>>(n, e);
    k_place<<<(e + 255) / 256, 256>>>(row, col, e);

    // layer 1: B1 = dis * (x @ W1); B2 = relu(dis * gather(B1) + b1)
    k_gemm<128><<<(n + 63) / 64, 256, SMEM>>>(x, W1, B1, n);
    k_gather128<<<(n * 32 + 255) / 256, 256>>>(B1, b1, B2, n, 1);

    // layer 2: B1 = dis * (B2 @ W2); out = dis * gather(B1) + b2
    k_gemm<64><<<(n + 127) / 128, 256, SMEM>>>(B2, W2, B1, n);
    k_gather64<<<(n * 32 + 255) / 256, 256>>>(B1, b2, out, n);
}

// round 3
// speedup vs baseline: 1.0743x; 1.0178x over previous
#include <cuda_runtime.h>
#include <cuda_bf16.h>
#include <math.h>

#define NN 50000
#define NE 800000
#define DI 128

typedef unsigned long long ull;

// ---------------- device scratch ----------------
__device__ float g_B1[NN * 128];   // unscaled hidden h = X@W
__device__ float g_B2[NN * 128];   // y1 = relu(...)
__device__ float g_dis[NN];        // deg^{-1/2} (incl self loop)
__device__ int   g_cnt[NN];
__device__ int   g_off[NN + 1];
__device__ int   g_cur[NN];
__device__ int   g_src[NE];

// ---------------- packed f32x2 helpers ----------------
__device__ __forceinline__ void ffma2(ull &d, ull a, ull b) {
    asm("fma.rn.f32x2 %0, %1, %2, %0;" : "+l"(d) : "l"(a), "l"(b));
}
__device__ __forceinline__ ull pack2(float x, float y) {
    ull r; asm("mov.b64 %0, {%1, %2};" : "=l"(r) : "f"(x), "f"(y)); return r;
}
__device__ __forceinline__ void unpack2(float &x, float &y, ull v) {
    asm("mov.b64 {%0, %1}, %2;" : "=f"(x), "=f"(y) : "l"(v));
}

// ---------------- CSR build ----------------
__global__ void k_hist(const int* __restrict__ col, int e4) {
    int i = blockIdx.x * blockDim.x + threadIdx.x;
    if (i < e4) {
        int4 c = ((const int4*)col)[i];
        atomicAdd(&g_cnt[c.x], 1);
        atomicAdd(&g_cnt[c.y], 1);
        atomicAdd(&g_cnt[c.z], 1);
        atomicAdd(&g_cnt[c.w], 1);
    }
}

__global__ void k_scan(int n, int e) {
    __shared__ int sbuf[1024];
    int tid = threadIdx.x;
    const int CH = (n + 1023) / 1024;
    int beg = tid * CH;
    int end = beg + CH; if (end > n) end = n;
    int sum = 0;
    for (int i = beg; i < end; i++) sum += g_cnt[i];
    sbuf[tid] = sum;
    __syncthreads();
    for (int d = 1; d < 1024; d <<= 1) {
        int t = (tid >= d) ? sbuf[tid - d] : 0;
        __syncthreads();
        sbuf[tid] += t;
        __syncthreads();
    }
    int base = sbuf[tid] - sum;  // exclusive prefix
    for (int i = beg; i < end; i++) {
        int c = g_cnt[i];
        g_off[i] = base;
        g_cur[i] = base;
        g_dis[i] = rsqrtf((float)(c + 1));
        base += c;
    }
    if (tid == 0) g_off[n] = e;
}

__global__ void k_place(const int* __restrict__ row, const int* __restrict__ col, int e4) {
    int i = blockIdx.x * blockDim.x + threadIdx.x;
    if (i < e4) {
        int4 r4 = ((const int4*)row)[i];
        int4 c4 = ((const int4*)col)[i];
        int p;
        p = atomicAdd(&g_cur[c4.x], 1); g_src[p] = r4.x;
        p = atomicAdd(&g_cur[c4.y], 1); g_src[p] = r4.y;
        p = atomicAdd(&g_cur[c4.z], 1); g_src[p] = r4.z;
        p = atomicAdd(&g_cur[c4.w], 1); g_src[p] = r4.w;
    }
}

// ---------------- GEMM via fma.rn.f32x2, row-pair packing ----------------
// out = A @ W (unscaled). Block 256 threads, thread tile 8 rows x 4 cols.
// Xs transposed [k][ROWS_T]: a row-pairs come packed straight from LDS.128.
// b duplicated with 4 movs per k, reused across 8 rows.
template<int NOUT>
__global__ void __launch_bounds__(256, 2) k_gemm(const float* __restrict__ A,
                                                 const float* __restrict__ W,
                                                 float* __restrict__ outp, int n) {
    constexpr int COLG   = NOUT / 4;      // 32 or 16 col groups
    constexpr int RG     = 256 / COLG;    // 8 or 16 row groups
    constexpr int ROWS_T = RG * 8;        // 64 or 128 rows per tile

    extern __shared__ float smem[];
    float* Xs  = smem;                    // [128][ROWS_T] transposed
    float* Wsh = smem + 128 * ROWS_T;     // [128][NOUT]

    int tid  = threadIdx.x;
    int row0 = blockIdx.x * ROWS_T;

    // stage W
    {
        const float4* W4 = (const float4*)W;
        float4* Wsh4 = (float4*)Wsh;
        #pragma unroll
        for (int i = 0; i < NOUT / 8; i++) {
            int idx = tid + i * 256;
            Wsh4[idx] = W4[idx];
        }
    }
    // stage X transposed
    {
        const float4* A4 = (const float4*)A;
        #pragma unroll
        for (int i = 0; i < ROWS_T / 8; i++) {
            int idx = tid + i * 256;
            int r = idx % ROWS_T;
            int c = idx / ROWS_T;
            float4 v = make_float4(0.f, 0.f, 0.f, 0.f);
            if (row0 + r < n) v = A4[(size_t)(row0 + r) * 32 + c];
            Xs[(4 * c + 0) * ROWS_T + r] = v.x;
            Xs[(4 * c + 1) * ROWS_T + r] = v.y;
            Xs[(4 * c + 2) * ROWS_T + r] = v.z;
            Xs[(4 * c + 3) * ROWS_T + r] = v.w;
        }
    }
    __syncthreads();

    int cg = tid % COLG;
    int rg = tid / COLG;

    ull acc[16];
    #pragma unroll
    for (int i = 0; i < 16; i++) acc[i] = 0ull;

    #pragma unroll 4
    for (int k = 0; k < 128; k++) {
        const float* xr = &Xs[k * ROWS_T + rg * 8];
        ulonglong2 va = *(const ulonglong2*)xr;        // row pairs (0,1),(2,3)
        ulonglong2 vb = *(const ulonglong2*)(xr + 4);  // row pairs (4,5),(6,7)
        float4 w = *(const float4*)&Wsh[k * NOUT + cg * 4];
        ull b0 = pack2(w.x, w.x);
        ull b1 = pack2(w.y, w.y);
        ull b2 = pack2(w.z, w.z);
        ull b3 = pack2(w.w, w.w);
        ffma2(acc[0],  va.x, b0); ffma2(acc[1],  va.x, b1);
        ffma2(acc[2],  va.x, b2); ffma2(acc[3],  va.x, b3);
        ffma2(acc[4],  va.y, b0); ffma2(acc[5],  va.y, b1);
        ffma2(acc[6],  va.y, b2); ffma2(acc[7],  va.y, b3);
        ffma2(acc[8],  vb.x, b0); ffma2(acc[9],  vb.x, b1);
        ffma2(acc[10], vb.x, b2); ffma2(acc[11], vb.x, b3);
        ffma2(acc[12], vb.y, b0); ffma2(acc[13], vb.y, b1);
        ffma2(acc[14], vb.y, b2); ffma2(acc[15], vb.y, b3);
    }

    // epilogue: unpack row pairs, store float4 per row (unscaled)
    float4* O4 = (float4*)outp;
    #pragma unroll
    for (int rp = 0; rp < 4; rp++) {
        float e0, e1, e2, e3, o0, o1, o2, o3;
        unpack2(e0, o0, acc[rp * 4 + 0]);
        unpack2(e1, o1, acc[rp * 4 + 1]);
        unpack2(e2, o2, acc[rp * 4 + 2]);
        unpack2(e3, o3, acc[rp * 4 + 3]);
        int r0 = row0 + rg * 8 + rp * 2;
        if (r0 < n)     O4[(size_t)r0 * (NOUT / 4) + cg] = make_float4(e0, e1, e2, e3);
        if (r0 + 1 < n) O4[(size_t)(r0 + 1) * (NOUT / 4) + cg] = make_float4(o0, o1, o2, o3);
    }
}

// ---------------- gather (warp per node), normalization applied here ----------------
// out[v] = act( dis[v] * ( dis[v]*h[v] + sum_{r in N(v)} dis[r]*h[r] ) + bias )
__global__ void k_gather128(const float* __restrict__ hs, const float* __restrict__ bias,
                            float* __restrict__ outp, int n, int relu) {
    int w = (blockIdx.x * blockDim.x + threadIdx.x) >> 5;
    if (w >= n) return;
    int lane = threadIdx.x & 31;
    const float4* hs4 = (const float4*)hs;
    float dw = g_dis[w];
    float4 self = hs4[(size_t)w * 32 + lane];
    float4 acc = make_float4(self.x * dw, self.y * dw, self.z * dw, self.w * dw);
    int s = g_off[w], e = g_off[w + 1];
    int j = s;
    for (; j + 8 <= e; j += 8) {
        int r[8]; float d[8];
        #pragma unroll
        for (int i = 0; i < 8; i++) r[i] = __ldg(&g_src[j + i]);
        #pragma unroll
        for (int i = 0; i < 8; i++) d[i] = __ldg(&g_dis[r[i]]);
        #pragma unroll
        for (int i = 0; i < 8; i++) {
            float4 m = hs4[(size_t)r[i] * 32 + lane];
            acc.x = fmaf(d[i], m.x, acc.x);
            acc.y = fmaf(d[i], m.y, acc.y);
            acc.z = fmaf(d[i], m.z, acc.z);
            acc.w = fmaf(d[i], m.w, acc.w);
        }
    }
    for (; j < e; j++) {
        int r = __ldg(&g_src[j]);
        float d = __ldg(&g_dis[r]);
        float4 m = hs4[(size_t)r * 32 + lane];
        acc.x = fmaf(d, m.x, acc.x);
        acc.y = fmaf(d, m.y, acc.y);
        acc.z = fmaf(d, m.z, acc.z);
        acc.w = fmaf(d, m.w, acc.w);
    }
    float4 b = ((const float4*)bias)[lane];
    float4 o = make_float4(acc.x * dw + b.x, acc.y * dw + b.y,
                           acc.z * dw + b.z, acc.w * dw + b.w);
    if (relu) {
        o.x = fmaxf(o.x, 0.f); o.y = fmaxf(o.y, 0.f);
        o.z = fmaxf(o.z, 0.f); o.w = fmaxf(o.w, 0.f);
    }
    ((float4*)outp)[(size_t)w * 32 + lane] = o;
}

__global__ void k_gather64(const float* __restrict__ hs, const float* __restrict__ bias,
                           float* __restrict__ outp, int n) {
    int w = (blockIdx.x * blockDim.x + threadIdx.x) >> 5;
    if (w >= n) return;
    int lane = threadIdx.x & 31;
    const float2* hs2 = (const float2*)hs;
    float dw = g_dis[w];
    float2 self = hs2[(size_t)w * 32 + lane];
    float2 acc = make_float2(self.x * dw, self.y * dw);
    int s = g_off[w], e = g_off[w + 1];
    int j = s;
    for (; j + 8 <= e; j += 8) {
        int r[8]; float d[8];
        #pragma unroll
        for (int i = 0; i < 8; i++) r[i] = __ldg(&g_src[j + i]);
        #pragma unroll
        for (int i = 0; i < 8; i++) d[i] = __ldg(&g_dis[r[i]]);
        #pragma unroll
        for (int i = 0; i < 8; i++) {
            float2 m = hs2[(size_t)r[i] * 32 + lane];
            acc.x = fmaf(d[i], m.x, acc.x);
            acc.y = fmaf(d[i], m.y, acc.y);
        }
    }
    for (; j < e; j++) {
        int r = __ldg(&g_src[j]);
        float d = __ldg(&g_dis[r]);
        float2 m = hs2[(size_t)r * 32 + lane];
        acc.x = fmaf(d, m.x, acc.x);
        acc.y = fmaf(d, m.y, acc.y);
    }
    float2 b = ((const float2*)bias)[lane];
    float2 o = make_float2(acc.x * dw + b.x, acc.y * dw + b.y);
    ((float2*)outp)[(size_t)w * 32 + lane] = o;
}

// ---------------- launch ----------------
extern "C" void kernel_launch(void* const* d_in, const int* in_sizes, int n_in,
                              void* d_out, int out_size) {
    const float* x   = (const float*)d_in[0];
    const int*   ei  = (const int*)d_in[1];
    const float* W1  = (const float*)d_in[2];
    const float* b1  = (const float*)d_in[3];
    const float* W2  = (const float*)d_in[4];
    const float* b2  = (const float*)d_in[5];
    float* out = (float*)d_out;

    const int n = in_sizes[0] / DI;     // 50000
    const int e = in_sizes[1] / 2;      // 800000
    const int* row = ei;
    const int* col = ei + e;

    float* B1 = nullptr; float* B2 = nullptr; int* cnt = nullptr;
    cudaGetSymbolAddress((void**)&B1, g_B1);
    cudaGetSymbolAddress((void**)&B2, g_B2);
    cudaGetSymbolAddress((void**)&cnt, g_cnt);

    const int SMEM = 98304;   // identical for both template variants
    cudaFuncSetAttribute(k_gemm<128>, cudaFuncAttributeMaxDynamicSharedMemorySize, SMEM);
    cudaFuncSetAttribute(k_gemm<64>,  cudaFuncAttributeMaxDynamicSharedMemorySize, SMEM);

    // fork: GEMM1 (independent of graph structure) runs on side stream,
    // CSR build runs on the capture stream.
    cudaStream_t s1;
    cudaStreamCreate(&s1);
    cudaEvent_t evFork, evJoin;
    cudaEventCreateWithFlags(&evFork, cudaEventDisableTiming);
    cudaEventCreateWithFlags(&evJoin, cudaEventDisableTiming);

    cudaEventRecord(evFork, 0);
    cudaStreamWaitEvent(s1, evFork, 0);
    k_gemm<128><<<(n + 63) / 64, 256, SMEM, s1>>>(x, W1, B1, n);
    cudaEventRecord(evJoin, s1);

    // CSR build on capture stream
    cudaMemsetAsync(cnt, 0, n * sizeof(int));
    int e4 = e / 4;
    k_hist<<<(e4 + 255) / 256, 256>>>(col, e4);
    k_scan<<<1, 1024>>>(n, e);
    k_place<<<(e4 + 255) / 256, 256>>>(row, col, e4);

    // join, then the serial tail
    cudaStreamWaitEvent(0, evJoin, 0);
    k_gather128<<<(n * 32 + 255) / 256, 256>>>(B1, b1, B2, n, 1);
    k_gemm<64><<<(n + 127) / 128, 256, SMEM>>>(B2, W2, B1, n);
    k_gather64<<<(n * 32 + 255) / 256, 256>>>(B1, b2, out, n);

    cudaStreamDestroy(s1);
    cudaEventDestroy(evFork);
    cudaEventDestroy(evJoin);
}

// round 5
// speedup vs baseline: 1.2674x; 1.1797x over previous
#include <cuda_runtime.h>
#include <cuda_fp16.h>
#include <math.h>
#include <stdint.h>

#define NN 50000
#define NE 800000
#define DI 128

// ---------------- device scratch ----------------
__device__ float g_B1[NN * 128];   // hidden h = A@W (unscaled)
__device__ float g_B2[NN * 128];   // y1
__device__ float g_dis[NN];
__device__ int   g_cnt[NN];
__device__ int   g_off[NN + 1];
__device__ int   g_cur[NN];
__device__ int   g_src[NE];
// W images: fp16 split, [n][k] row-major, stride 136 halves; hi tile then lo tile
__device__ __align__(16) __half g_W1img[2 * 128 * 136];
__device__ __align__(16) __half g_W2img[2 * 64 * 136];

__device__ __forceinline__ uint32_t smem_u32(const void* p) {
    uint32_t a;
    asm("{ .reg .u64 t; cvta.to.shared.u64 t, %1; cvt.u32.u64 %0, t; }" : "=r"(a) : "l"(p));
    return a;
}

#define LDSM_X4(r0, r1, r2, r3, addr) \
    asm volatile("ldmatrix.sync.aligned.m8n8.x4.shared.b16 {%0,%1,%2,%3}, [%4];" \
                 : "=r"(r0), "=r"(r1), "=r"(r2), "=r"(r3) : "r"(addr))
#define LDSM_X2(r0, r1, addr) \
    asm volatile("ldmatrix.sync.aligned.m8n8.x2.shared.b16 {%0,%1}, [%2];" \
                 : "=r"(r0), "=r"(r1) : "r"(addr))

__device__ __forceinline__ void mma16816(float* c, const uint32_t* a, const uint32_t* b) {
    asm volatile(
        "mma.sync.aligned.m16n8k16.row.col.f32.f16.f16.f32 "
        "{%0,%1,%2,%3}, {%4,%5,%6,%7}, {%8,%9}, {%0,%1,%2,%3};"
        : "+f"(c[0]), "+f"(c[1]), "+f"(c[2]), "+f"(c[3])
        : "r"(a[0]), "r"(a[1]), "r"(a[2]), "r"(a[3]), "r"(b[0]), "r"(b[1]));
}

// ---------------- W image precompute ----------------
template<int NOUT>
__global__ void k_wconv(const float* __restrict__ W, __half* __restrict__ img) {
    constexpr int S = 136;
    int tid = threadIdx.x;
    for (int idx = tid; idx < NOUT * 128; idx += 256) {
        int nn = idx % NOUT;     // output col = B row
        int k  = idx / NOUT;     // K index
        float v = W[k * NOUT + nn];
        __half h = __float2half_rn(v);
        __half l = __float2half_rn(v - __half2float(h));
        img[nn * S + k] = h;
        img[NOUT * S + nn * S + k] = l;
    }
}

// ---------------- tensor GEMM via mma.sync, 3-term fp16 split ----------------
// out[n x NOUT] = A[n x 128] @ W[128 x NOUT], fp32 accuracy ~1e-6.
template<int NOUT>
__global__ void __launch_bounds__(256, 1) k_mgemm(const float* __restrict__ A,
                                                  const __half* __restrict__ Wimg,
                                                  float* __restrict__ outp, int n) {
    constexpr int S = 136;              // halves per row (128 + 8 pad)
    constexpr int SB = S * 2;           // bytes per row (272)
    constexpr int ASZ = 128 * S;        // halves per A tile
    constexpr int BSZ = NOUT * S;       // halves per B tile
    constexpr int MI = (NOUT == 128) ? 4 : 2;   // m16 frags per warp

    extern __shared__ __half sm[];
    __half* Ah = sm;
    __half* Al = sm + ASZ;
    __half* Bh = sm + 2 * ASZ;
    __half* Bl = sm + 2 * ASZ + BSZ;

    int tid = threadIdx.x, wid = tid >> 5, lane = tid & 31;
    int row0 = blockIdx.x * 128;

    // stage W images (hi+lo contiguous)
    {
        const uint4* src = (const uint4*)Wimg;
        uint4* dst = (uint4*)Bh;
        for (int i = tid; i < (2 * BSZ) / 8; i += 256) dst[i] = src[i];
    }
    // stage A with fp16 split
    {
        const float4* A4 = (const float4*)A;
        #pragma unroll
        for (int i = 0; i < 16; i++) {
            int idx = tid + i * 256;         // 0..4095 over 128 rows x 32 float4
            int r = idx >> 5;
            int c = idx & 31;
            float4 v = make_float4(0.f, 0.f, 0.f, 0.f);
            if (row0 + r < n) v = A4[(size_t)(row0 + r) * 32 + c];
            __half h0 = __float2half_rn(v.x), h1 = __float2half_rn(v.y);
            __half h2 = __float2half_rn(v.z), h3 = __float2half_rn(v.w);
            __half l0 = __float2half_rn(v.x - __half2float(h0));
            __half l1 = __float2half_rn(v.y - __half2float(h1));
            __half l2 = __float2half_rn(v.z - __half2float(h2));
            __half l3 = __float2half_rn(v.w - __half2float(h3));
            __half2 hp0 = __halves2half2(h0, h1), hp1 = __halves2half2(h2, h3);
            __half2 lp0 = __halves2half2(l0, l1), lp1 = __halves2half2(l2, l3);
            *(uint2*)&Ah[r * S + c * 4] = make_uint2(*(uint32_t*)&hp0, *(uint32_t*)&hp1);
            *(uint2*)&Al[r * S + c * 4] = make_uint2(*(uint32_t*)&lp0, *(uint32_t*)&lp1);
        }
    }
    __syncthreads();

    // warp tiling
    int m0w, n0w;
    if (NOUT == 128) { m0w = (wid >> 2) * 64; n0w = (wid & 3) * 32; }
    else             { m0w = (wid >> 1) * 32; n0w = (wid & 1) * 32; }

    float acc[MI][4][4] = {};

    uint32_t aAh = smem_u32(Ah), aAl = smem_u32(Al);
    uint32_t aBh = smem_u32(Bh), aBl = smem_u32(Bl);
    // A frag lane address: row m0w + (lane&15), +16B for lanes>=16 (k+8)
    uint32_t a_lane = (uint32_t)(m0w + (lane & 15)) * SB + ((lane >> 4) << 4);
    // B frag lane address (x2 uses lanes 0-15): row n0w + (l&7), +16B for l&8
    int bl = lane & 15;
    uint32_t b_lane = (uint32_t)(n0w + (bl & 7)) * SB + ((bl >> 3) << 4);

    #pragma unroll
    for (int t = 0; t < 3; t++) {
        uint32_t aA = (t == 2) ? aAl : aAh;
        uint32_t aB = (t == 1) ? aBl : aBh;
        #pragma unroll
        for (int k0 = 0; k0 < 128; k0 += 16) {
            uint32_t ar[MI][4];
            #pragma unroll
            for (int mi = 0; mi < MI; mi++) {
                uint32_t ad = aA + a_lane + (uint32_t)(mi * 16) * SB + k0 * 2;
                LDSM_X4(ar[mi][0], ar[mi][1], ar[mi][2], ar[mi][3], ad);
            }
            #pragma unroll
            for (int nj = 0; nj < 4; nj++) {
                uint32_t br[2];
                uint32_t bd = aB + b_lane + (uint32_t)(nj * 8) * SB + k0 * 2;
                LDSM_X2(br[0], br[1], bd);
                #pragma unroll
                for (int mi = 0; mi < MI; mi++) mma16816(acc[mi][nj], ar[mi], br);
            }
        }
    }

    // epilogue: C frag layout — c0,c1 at row l/4, cols (l%4)*2; c2,c3 at row+8
    #pragma unroll
    for (int mi = 0; mi < MI; mi++) {
        int r = row0 + m0w + mi * 16 + (lane >> 2);
        #pragma unroll
        for (int nj = 0; nj < 4; nj++) {
            int c = n0w + nj * 8 + (lane & 3) * 2;
            if (r < n)
                *(float2*)&outp[(size_t)r * NOUT + c] = make_float2(acc[mi][nj][0], acc[mi][nj][1]);
            if (r + 8 < n)
                *(float2*)&outp[(size_t)(r + 8) * NOUT + c] = make_float2(acc[mi][nj][2], acc[mi][nj][3]);
        }
    }
}

// ---------------- CSR build ----------------
__global__ void k_hist(const int* __restrict__ col, int e4) {
    int i = blockIdx.x * blockDim.x + threadIdx.x;
    if (i < e4) {
        int4 c = ((const int4*)col)[i];
        atomicAdd(&g_cnt[c.x], 1);
        atomicAdd(&g_cnt[c.y], 1);
        atomicAdd(&g_cnt[c.z], 1);
        atomicAdd(&g_cnt[c.w], 1);
    }
}

__global__ void k_scan(int n, int e) {
    __shared__ int sbuf[1024];
    int tid = threadIdx.x;
    const int CH = (n + 1023) / 1024;
    int beg = tid * CH;
    int end = beg + CH; if (end > n) end = n;
    int sum = 0;
    for (int i = beg; i < end; i++) sum += g_cnt[i];
    sbuf[tid] = sum;
    __syncthreads();
    for (int d = 1; d < 1024; d <<= 1) {
        int t = (tid >= d) ? sbuf[tid - d] : 0;
        __syncthreads();
        sbuf[tid] += t;
        __syncthreads();
    }
    int base = sbuf[tid] - sum;
    for (int i = beg; i < end; i++) {
        int c = g_cnt[i];
        g_off[i] = base;
        g_cur[i] = base;
        g_dis[i] = rsqrtf((float)(c + 1));
        base += c;
    }
    if (tid == 0) g_off[n] = e;
}

__global__ void k_place(const int* __restrict__ row, const int* __restrict__ col, int e4) {
    int i = blockIdx.x * blockDim.x + threadIdx.x;
    if (i < e4) {
        int4 r4 = ((const int4*)row)[i];
        int4 c4 = ((const int4*)col)[i];
        int p;
        p = atomicAdd(&g_cur[c4.x], 1); g_src[p] = r4.x;
        p = atomicAdd(&g_cur[c4.y], 1); g_src[p] = r4.y;
        p = atomicAdd(&g_cur[c4.z], 1); g_src[p] = r4.z;
        p = atomicAdd(&g_cur[c4.w], 1); g_src[p] = r4.w;
    }
}

// ---------------- gathers (warp per node) ----------------
__global__ void k_gather128(const float* __restrict__ hs, const float* __restrict__ bias,
                            float* __restrict__ outp, int n, int relu) {
    int w = (blockIdx.x * blockDim.x + threadIdx.x) >> 5;
    if (w >= n) return;
    int lane = threadIdx.x & 31;
    const float4* hs4 = (const float4*)hs;
    float dw = g_dis[w];
    float4 self = hs4[(size_t)w * 32 + lane];
    float4 acc = make_float4(self.x * dw, self.y * dw, self.z * dw, self.w * dw);
    int s = g_off[w], e = g_off[w + 1];
    int j = s;
    for (; j + 8 <= e; j += 8) {
        int r[8]; float d[8];
        #pragma unroll
        for (int i = 0; i < 8; i++) r[i] = __ldg(&g_src[j + i]);
        #pragma unroll
        for (int i = 0; i < 8; i++) d[i] = __ldg(&g_dis[r[i]]);
        #pragma unroll
        for (int i = 0; i < 8; i++) {
            float4 m = hs4[(size_t)r[i] * 32 + lane];
            acc.x = fmaf(d[i], m.x, acc.x);
            acc.y = fmaf(d[i], m.y, acc.y);
            acc.z = fmaf(d[i], m.z, acc.z);
            acc.w = fmaf(d[i], m.w, acc.w);
        }
    }
    for (; j < e; j++) {
        int r = __ldg(&g_src[j]);
        float d = __ldg(&g_dis[r]);
        float4 m = hs4[(size_t)r * 32 + lane];
        acc.x = fmaf(d, m.x, acc.x);
        acc.y = fmaf(d, m.y, acc.y);
        acc.z = fmaf(d, m.z, acc.z);
        acc.w = fmaf(d, m.w, acc.w);
    }
    float4 b = ((const float4*)bias)[lane];
    float4 o = make_float4(acc.x * dw + b.x, acc.y * dw + b.y,
                           acc.z * dw + b.z, acc.w * dw + b.w);
    if (relu) {
        o.x = fmaxf(o.x, 0.f); o.y = fmaxf(o.y, 0.f);
        o.z = fmaxf(o.z, 0.f); o.w = fmaxf(o.w, 0.f);
    }
    ((float4*)outp)[(size_t)w * 32 + lane] = o;
}

__global__ void k_gather64(const float* __restrict__ hs, const float* __restrict__ bias,
                           float* __restrict__ outp, int n) {
    int w = (blockIdx.x * blockDim.x + threadIdx.x) >> 5;
    if (w >= n) return;
    int lane = threadIdx.x & 31;
    const float2* hs2 = (const float2*)hs;
    float dw = g_dis[w];
    float2 self = hs2[(size_t)w * 32 + lane];
    float2 acc = make_float2(self.x * dw, self.y * dw);
    int s = g_off[w], e = g_off[w + 1];
    int j = s;
    for (; j + 8 <= e; j += 8) {
        int r[8]; float d[8];
        #pragma unroll
        for (int i = 0; i < 8; i++) r[i] = __ldg(&g_src[j + i]);
        #pragma unroll
        for (int i = 0; i < 8; i++) d[i] = __ldg(&g_dis[r[i]]);
        #pragma unroll
        for (int i = 0; i < 8; i++) {
            float2 m = hs2[(size_t)r[i] * 32 + lane];
            acc.x = fmaf(d[i], m.x, acc.x);
            acc.y = fmaf(d[i], m.y, acc.y);
        }
    }
    for (; j < e; j++) {
        int r = __ldg(&g_src[j]);
        float d = __ldg(&g_dis[r]);
        float2 m = hs2[(size_t)r * 32 + lane];
        acc.x = fmaf(d, m.x, acc.x);
        acc.y = fmaf(d, m.y, acc.y);
    }
    float2 b = ((const float2*)bias)[lane];
    float2 o = make_float2(acc.x * dw + b.x, acc.y * dw + b.y);
    ((float2*)outp)[(size_t)w * 32 + lane] = o;
}

// ---------------- launch ----------------
extern "C" void kernel_launch(void* const* d_in, const int* in_sizes, int n_in,
                              void* d_out, int out_size) {
    const float* x   = (const float*)d_in[0];
    const int*   ei  = (const int*)d_in[1];
    const float* W1  = (const float*)d_in[2];
    const float* b1  = (const float*)d_in[3];
    const float* W2  = (const float*)d_in[4];
    const float* b2  = (const float*)d_in[5];
    float* out = (float*)d_out;

    const int n = in_sizes[0] / DI;     // 50000
    const int e = in_sizes[1] / 2;      // 800000
    const int* row = ei;
    const int* col = ei + e;

    float* B1; float* B2; int* cnt; __half *W1img, *W2img;
    cudaGetSymbolAddress((void**)&B1, g_B1);
    cudaGetSymbolAddress((void**)&B2, g_B2);
    cudaGetSymbolAddress((void**)&cnt, g_cnt);
    cudaGetSymbolAddress((void**)&W1img, g_W1img);
    cudaGetSymbolAddress((void**)&W2img, g_W2img);

    // dyn smem: 2 A tiles + 2 B tiles, stride 136 halves
    const int SM1 = (2 * 128 * 136 + 2 * 128 * 136) * 2;   // 139264
    const int SM2 = (2 * 128 * 136 + 2 * 64 * 136) * 2;    // 104448
    cudaFuncSetAttribute(k_mgemm<128>, cudaFuncAttributeMaxDynamicSharedMemorySize, SM1);
    cudaFuncSetAttribute(k_mgemm<64>,  cudaFuncAttributeMaxDynamicSharedMemorySize, SM2);

    cudaStream_t s1;
    cudaStreamCreate(&s1);
    cudaEvent_t evFork, evJoin;
    cudaEventCreateWithFlags(&evFork, cudaEventDisableTiming);
    cudaEventCreateWithFlags(&evJoin, cudaEventDisableTiming);

    int nblk = (n + 127) / 128;

    // side stream: W conversions + GEMM1
    cudaEventRecord(evFork, 0);
    cudaStreamWaitEvent(s1, evFork, 0);
    k_wconv<128><<<1, 256, 0, s1>>>(W1, W1img);
    k_wconv<64><<<1, 256, 0, s1>>>(W2, W2img);
    k_mgemm<128><<<nblk, 256, SM1, s1>>>(x, W1img, B1, n);
    cudaEventRecord(evJoin, s1);

    // capture stream: CSR build
    cudaMemsetAsync(cnt, 0, n * sizeof(int));
    int e4 = e / 4;
    k_hist<<<(e4 + 255) / 256, 256>>>(col, e4);
    k_scan<<<1, 1024>>>(n, e);
    k_place<<<(e4 + 255) / 256, 256>>>(row, col, e4);

    cudaStreamWaitEvent(0, evJoin, 0);
    k_gather128<<<(n * 32 + 255) / 256, 256>>>(B1, b1, B2, n, 1);
    k_mgemm<64><<<nblk, 256, SM2>>>(B2, W2img, B1, n);
    k_gather64<<<(n * 32 + 255) / 256, 256>>>(B1, b2, out, n);

    cudaStreamDestroy(s1);
    cudaEventDestroy(evFork);
    cudaEventDestroy(evJoin);
}